// round 12
// baseline (speedup 1.0000x reference)
#include <cuda_runtime.h>
#include <math.h>
#include <stdint.h>

#define Nn 50000
#define Ee 600000
#define Hh 128
#define Cc 40

// ---------------- scratch (static device globals; no allocation) ----------------
__device__ int   g_deg[Nn];
__device__ int   g_row_ptr[Nn + 1];
__device__ int   g_cursor[Nn];
__device__ int   g_col[Ee];
__device__ float g_inv_deg[Nn];
__device__ int   g_bsums[64];
__device__ int   g_is64;
__device__ int   g_tctr[4];    // gemm tile counters
__device__ int   g_actr[3];    // aggregate node counters
__device__ float g_agg[(size_t)Nn * Hh];
__device__ float g_h1[(size_t)Nn * Hh];
__device__ float g_h2[(size_t)Nn * Hh];

// buffer selectors: 0 = g_agg, 1 = g_h1, 2 = g_h2, 3 = external x
__device__ __forceinline__ const float* rd_buf(int sel, const float* x) {
    switch (sel) {
        case 0: return g_agg;
        case 1: return g_h1;
        case 2: return g_h2;
        default: return x;
    }
}
__device__ __forceinline__ float* wr_buf(int sel) {
    switch (sel) {
        case 0: return g_agg;
        case 1: return g_h1;
        default: return g_h2;
    }
}

__device__ __forceinline__ int edge_at(const void* ei, int is64, long long idx) {
    if (is64) return (int)((const long long*)ei)[idx];
    return ((const int*)ei)[idx];
}

// ---------------- dtype detect + zero deg + zero counters ----------------
__global__ void detect_zero_kernel(const void* __restrict__ ei) {
    int i = blockIdx.x * blockDim.x + threadIdx.x;
    if (i < Nn) g_deg[i] = 0;
    if (blockIdx.x == 0) {
        if (threadIdx.x < 4) g_tctr[threadIdx.x] = 0;
        if (threadIdx.x >= 4 && threadIdx.x < 7) g_actr[threadIdx.x - 4] = 0;
        if (threadIdx.x == 31) {
            const long long* p64 = (const long long*)ei;
            int ok64 = 1;
            for (int k = 0; k < 64; k++) {
                long long v = p64[k];
                if (v < 0 || v >= Nn) { ok64 = 0; break; }
            }
            g_is64 = ok64;
        }
    }
}

// ---------------- CSR build ----------------
__global__ void count_deg_kernel(const void* __restrict__ ei) {
    int e = blockIdx.x * blockDim.x + threadIdx.x;
    if (e < Ee) {
        int dst = edge_at(ei, g_is64, (long long)Ee + e);
        atomicAdd(&g_deg[dst], 1);
    }
}

__global__ void scan_blocks_kernel() {
    __shared__ int s[1024];
    int t = threadIdx.x;
    int i = blockIdx.x * 1024 + t;
    int v = (i < Nn) ? g_deg[i] : 0;
    s[t] = v;
    __syncthreads();
    for (int off = 1; off < 1024; off <<= 1) {
        int add = (t >= off) ? s[t - off] : 0;
        __syncthreads();
        s[t] += add;
        __syncthreads();
    }
    if (i < Nn) g_row_ptr[i + 1] = s[t];
    if (t == 1023) g_bsums[blockIdx.x] = s[1023];
}

__global__ void scan_sums_kernel(int nb) {
    if (threadIdx.x == 0 && blockIdx.x == 0) {
        int acc = 0;
        for (int i = 0; i < nb; i++) { int tt = g_bsums[i]; g_bsums[i] = acc; acc += tt; }
    }
}

__global__ void scan_finalize_kernel() {
    int i = blockIdx.x * 1024 + threadIdx.x;
    if (i < Nn) {
        int incl = g_row_ptr[i + 1] + g_bsums[blockIdx.x];
        g_row_ptr[i + 1] = incl;
        int d = g_deg[i];
        g_cursor[i] = incl - d;
        g_inv_deg[i] = 1.0f / (float)(d > 1 ? d : 1);
        if (i == 0) g_row_ptr[0] = 0;
    }
}

__global__ void fill_csr_kernel(const void* __restrict__ ei) {
    int e = blockIdx.x * blockDim.x + threadIdx.x;
    if (e < Ee) {
        int is64 = g_is64;
        int dst = edge_at(ei, is64, (long long)Ee + e);
        int src = edge_at(ei, is64, e);
        int pos = atomicAdd(&g_cursor[dst], 1);
        g_col[pos] = src;
    }
}

// ---------------- mean aggregation: warp-dynamic, 2 nodes per pop ----------------
__global__ __launch_bounds__(256) void aggregate_kernel(int ctr, int selIn,
                                                        const float* __restrict__ x) {
    const float* in = rd_buf(selIn, x);
    const int lane = threadIdx.x & 31;
    for (;;) {
        int base;
        if (lane == 0) base = atomicAdd(&g_actr[ctr], 2);
        base = __shfl_sync(0xffffffffu, base, 0);
        if (base >= Nn) break;
#pragma unroll
        for (int u = 0; u < 2; u++) {
            int node = base + u;
            if (node >= Nn) break;
            int s = g_row_ptr[node];
            int e = g_row_ptr[node + 1];
            float4 acc = make_float4(0.f, 0.f, 0.f, 0.f);
            for (int i = s; i < e; i++) {
                int nbr = g_col[i];
                float4 v = *(const float4*)(in + (size_t)nbr * Hh + lane * 4);
                acc.x += v.x; acc.y += v.y; acc.z += v.z; acc.w += v.w;
            }
            float id = g_inv_deg[node];
            acc.x *= id; acc.y *= id; acc.z *= id; acc.w *= id;
            *(float4*)(g_agg + (size_t)node * Hh + lane * 4) = acc;
        }
    }
}

// ---------------- tf32 tensor-core dual GEMM: persistent + dynamic tiles -------
// C = relu(A1@W1 [+ A2@W2] + b); BM=128,BN=128,BK=16; 8 warps, warp tile 32x64.
__global__ __launch_bounds__(256, 2) void gemm_tf32_kernel(
    int ctr, int selA1, const float* __restrict__ W1,
    int selA2, const float* __restrict__ W2,
    const float* __restrict__ bias, int selC,
    const float* __restrict__ x, int M)
{
    const float* A1 = rd_buf(selA1, x);
    const float* A2 = (selA2 < 0) ? A1 : rd_buf(selA2, x);
    float* C = wr_buf(selC);

    __shared__ float As[2][128][20];
    __shared__ float Bs[2][16][128];
    __shared__ int s_tile;

    const int t = threadIdx.x;
    const int lane = t & 31;
    const int warp = t >> 5;
    const int g = lane >> 2;
    const int tig = lane & 3;
    const int warpM = warp & 3;
    const int warpN = warp >> 2;
    const int nTiles = (M + 127) / 128;
    const int nIter = (selA2 >= 0) ? 16 : 8;

    uint32_t asA = (uint32_t)__cvta_generic_to_shared(&As[0][0][0]);
    uint32_t asB = (uint32_t)__cvta_generic_to_shared(&Bs[0][0][0]);

    for (;;) {
        __syncthreads();                       // smem + s_tile reuse guard
        if (t == 0) s_tile = atomicAdd(&g_tctr[ctr], 1);
        __syncthreads();
        const int tile = s_tile;
        if (tile >= nTiles) break;
        const int block_row = tile * 128;

        float acc[2][8][4];
#pragma unroll
        for (int mt = 0; mt < 2; mt++)
#pragma unroll
            for (int nt = 0; nt < 8; nt++)
#pragma unroll
                for (int i = 0; i < 4; i++) acc[mt][nt][i] = 0.f;

        auto issue = [&](int it, int s) {
            const float* Ap = (it < 8) ? A1 : A2;
            const float* Wp = (it < 8) ? W1 : W2;
            const int kk = (it & 7) * 16;
#pragma unroll
            for (int i = 0; i < 2; i++) {
                int idx = t + i * 256;
                int r = idx >> 2;
                int c4 = (idx & 3) * 4;
                int gr = block_row + r;
                int grc = (gr < M) ? gr : (M - 1);
                const float* src = Ap + (size_t)grc * 128 + kk + c4;
                uint32_t dst = asA + (uint32_t)(((s * 128 + r) * 20 + c4) * 4);
                int sz = (gr < M) ? 16 : 0;
                asm volatile("cp.async.cg.shared.global [%0], [%1], 16, %2;"
                             :: "r"(dst), "l"(src), "r"(sz));
            }
#pragma unroll
            for (int i = 0; i < 2; i++) {
                int idx = t + i * 256;
                int kr = idx >> 5;
                int n = (idx & 31) * 4;
                const float* src = Wp + (size_t)(kk + kr) * 128 + n;
                int pc = n ^ ((kr & 3) << 3);
                uint32_t dst = asB + (uint32_t)(((s * 16 + kr) * 128 + pc) * 4);
                asm volatile("cp.async.cg.shared.global [%0], [%1], 16;"
                             :: "r"(dst), "l"(src));
            }
            asm volatile("cp.async.commit_group;");
        };

        issue(0, 0);

        for (int it = 0; it < nIter; it++) {
            const int s = it & 1;
            if (it + 1 < nIter) {
                issue(it + 1, (it + 1) & 1);
                asm volatile("cp.async.wait_group 1;");
            } else {
                asm volatile("cp.async.wait_group 0;");
            }
            __syncthreads();

#pragma unroll
            for (int ks = 0; ks < 2; ks++) {
                const int kc = ks * 8 + tig;
                uint32_t af[2][4];
#pragma unroll
                for (int mt = 0; mt < 2; mt++) {
                    int rb = warpM * 32 + mt * 16;
                    af[mt][0] = __float_as_uint(As[s][rb + g][kc]);
                    af[mt][1] = __float_as_uint(As[s][rb + g + 8][kc]);
                    af[mt][2] = __float_as_uint(As[s][rb + g][kc + 4]);
                    af[mt][3] = __float_as_uint(As[s][rb + g + 8][kc + 4]);
                }
                uint32_t bf[8][2];
                const int sw = (tig & 3) << 3;
#pragma unroll
                for (int nt = 0; nt < 8; nt++) {
                    int nb = warpN * 64 + nt * 8 + g;
                    bf[nt][0] = __float_as_uint(Bs[s][kc][nb ^ sw]);
                    bf[nt][1] = __float_as_uint(Bs[s][kc + 4][nb ^ sw]);
                }
#pragma unroll
                for (int mt = 0; mt < 2; mt++)
#pragma unroll
                    for (int nt = 0; nt < 8; nt++) {
                        asm volatile(
                            "mma.sync.aligned.m16n8k8.row.col.f32.tf32.tf32.f32 "
                            "{%0,%1,%2,%3}, {%4,%5,%6,%7}, {%8,%9}, {%0,%1,%2,%3};"
                            : "+f"(acc[mt][nt][0]), "+f"(acc[mt][nt][1]),
                              "+f"(acc[mt][nt][2]), "+f"(acc[mt][nt][3])
                            : "r"(af[mt][0]), "r"(af[mt][1]), "r"(af[mt][2]), "r"(af[mt][3]),
                              "r"(bf[nt][0]), "r"(bf[nt][1]));
                    }
            }
            __syncthreads();
        }

        // epilogue: bias + relu
#pragma unroll
        for (int mt = 0; mt < 2; mt++) {
            int r0 = block_row + warpM * 32 + mt * 16 + g;
            int r1 = r0 + 8;
#pragma unroll
            for (int nt = 0; nt < 8; nt++) {
                int c0 = warpN * 64 + nt * 8 + 2 * tig;
                float2 bv = *(const float2*)(bias + c0);
                if (r0 < M) {
                    float2 o;
                    o.x = fmaxf(acc[mt][nt][0] + bv.x, 0.f);
                    o.y = fmaxf(acc[mt][nt][1] + bv.y, 0.f);
                    *(float2*)(C + (size_t)r0 * 128 + c0) = o;
                }
                if (r1 < M) {
                    float2 o;
                    o.x = fmaxf(acc[mt][nt][2] + bv.x, 0.f);
                    o.y = fmaxf(acc[mt][nt][3] + bv.y, 0.f);
                    *(float2*)(C + (size_t)r1 * 128 + c0) = o;
                }
            }
        }
    }
}

// ---------------- fused lin2 + log_softmax: 32 rows per block ----------------
__global__ __launch_bounds__(320) void lin2_logsoftmax_kernel(
    const float* __restrict__ W, const float* __restrict__ b,
    float* __restrict__ outp, int M)
{
    __shared__ float Ws[128 * 40];
    __shared__ float bs[40];
    __shared__ float hs[32][128];
    __shared__ float logits[32][40];
    __shared__ float rmax[32], rlse[32];

    const int t = threadIdx.x;
    for (int i = t; i < 128 * 40; i += 320) Ws[i] = W[i];
    if (t < 40) bs[t] = b[t];

    const int row0 = blockIdx.x * 32;
    for (int i = t; i < 32 * 128; i += 320) {
        int r = i >> 7, c = i & 127;
        int gr = row0 + r;
        hs[r][c] = (gr < M) ? g_h2[(size_t)gr * 128 + c] : 0.f;
    }
    __syncthreads();

    const int j = t % 40;
    const int r0 = t / 40;
    float acc[4];
#pragma unroll
    for (int rr = 0; rr < 4; rr++) acc[rr] = bs[j];
#pragma unroll
    for (int k = 0; k < 128; k++) {
        float w = Ws[k * 40 + j];
#pragma unroll
        for (int rr = 0; rr < 4; rr++)
            acc[rr] += hs[r0 + rr * 8][k] * w;
    }
#pragma unroll
    for (int rr = 0; rr < 4; rr++)
        logits[r0 + rr * 8][j] = acc[rr];
    __syncthreads();

    if (t < 32) {
        float m = -1e30f;
#pragma unroll
        for (int jj = 0; jj < 40; jj++) m = fmaxf(m, logits[t][jj]);
        float s = 0.f;
#pragma unroll
        for (int jj = 0; jj < 40; jj++) s += expf(logits[t][jj] - m);
        rmax[t] = m;
        rlse[t] = logf(s);
    }
    __syncthreads();

#pragma unroll
    for (int rr = 0; rr < 4; rr++) {
        int r = r0 + rr * 8;
        int gr = row0 + r;
        if (gr < M)
            outp[(size_t)gr * 40 + j] = logits[r][j] - rmax[r] - rlse[r];
    }
}

// ---------------- launcher ----------------
extern "C" void kernel_launch(void* const* d_in, const int* in_sizes, int n_in,
                              void* d_out, int out_size) {
    const float* x  = (const float*)d_in[0];
    const void*  ei = d_in[1];
    const float *Wl1 = (const float*)d_in[2],  *bl1 = (const float*)d_in[3],  *Wr1 = (const float*)d_in[4];
    const float *Wl2 = (const float*)d_in[5],  *bl2 = (const float*)d_in[6],  *Wr2 = (const float*)d_in[7];
    const float *Wl3 = (const float*)d_in[8],  *bl3 = (const float*)d_in[9],  *Wr3 = (const float*)d_in[10];
    const float *Wlin1 = (const float*)d_in[11], *blin1 = (const float*)d_in[12];
    const float *Wlin2 = (const float*)d_in[13], *blin2 = (const float*)d_in[14];
    float* outp = (float*)d_out;

    const int TB = 256;
    const int edge_blocks = (Ee + TB - 1) / TB;
    const int node_blocks_1024 = (Nn + 1023) / 1024;
    const int node_blocks_256 = (Nn + 255) / 256;
    const int agg_grid = 148 * 8;        // persistent-ish, dynamic node pops
    const int gemm_grid = 148 * 2;       // persistent, dynamic tile pops
    const int sm_blocks = (Nn + 31) / 32;

    // ---- CSR build ----
    detect_zero_kernel<<<node_blocks_256, TB>>>(ei);
    count_deg_kernel<<<edge_blocks, TB>>>(ei);
    scan_blocks_kernel<<<node_blocks_1024, 1024>>>();
    scan_sums_kernel<<<1, 32>>>(node_blocks_1024);
    scan_finalize_kernel<<<node_blocks_1024, 1024>>>();
    fill_csr_kernel<<<edge_blocks, TB>>>(ei);

    // selectors: 0 = g_agg, 1 = g_h1, 2 = g_h2, 3 = x
    // ---- layer 1 ----
    aggregate_kernel<<<agg_grid, TB>>>(0, 3, x);
    gemm_tf32_kernel<<<gemm_grid, 256>>>(0, 0, Wl1, 3, Wr1, bl1, 1, x, Nn);
    // ---- layer 2 ----
    aggregate_kernel<<<agg_grid, TB>>>(1, 1, x);
    gemm_tf32_kernel<<<gemm_grid, 256>>>(1, 0, Wl2, 1, Wr2, bl2, 2, x, Nn);
    // ---- layer 3 ----
    aggregate_kernel<<<agg_grid, TB>>>(2, 2, x);
    gemm_tf32_kernel<<<gemm_grid, 256>>>(2, 0, Wl3, 2, Wr3, bl3, 1, x, Nn);
    // ---- lin1 + relu ----
    gemm_tf32_kernel<<<gemm_grid, 256>>>(3, 1, Wlin1, -1, nullptr, blin1, 2, x, Nn);
    // ---- lin2 + log_softmax ----
    lin2_logsoftmax_kernel<<<sm_blocks, 320>>>(Wlin2, blin2, outp, Nn);
}

// round 13
// speedup vs baseline: 1.1469x; 1.1469x over previous
#include <cuda_runtime.h>
#include <cuda_fp16.h>
#include <math.h>
#include <stdint.h>

#define Nn 50000
#define Ee 600000
#define Hh 128
#define Cc 40

// ---------------- scratch (static device globals; no allocation) ----------------
__device__ int     g_deg[Nn];
__device__ int     g_row_ptr[Nn + 1];
__device__ int     g_cursor[Nn];
__device__ int     g_col[Ee];
__device__ float   g_inv_deg[Nn];
__device__ int     g_bsums[64];
__device__ int     g_is64;
__device__ float   g_agg[(size_t)Nn * Hh];
__device__ float   g_h1[(size_t)Nn * Hh];
__device__ float   g_h2[(size_t)Nn * Hh];
__device__ __half2 g_h16[(size_t)Nn * Hh / 2];   // fp16 copy of current features (agg operand)

// buffer selectors: 0 = g_agg, 1 = g_h1, 2 = g_h2, 3 = external x
__device__ __forceinline__ const float* rd_buf(int sel, const float* x) {
    switch (sel) {
        case 0: return g_agg;
        case 1: return g_h1;
        case 2: return g_h2;
        default: return x;
    }
}
__device__ __forceinline__ float* wr_buf(int sel) {
    switch (sel) {
        case 0: return g_agg;
        case 1: return g_h1;
        default: return g_h2;
    }
}

__device__ __forceinline__ int edge_at(const void* ei, int is64, long long idx) {
    if (is64) return (int)((const long long*)ei)[idx];
    return ((const int*)ei)[idx];
}

// ---------------- dtype detect + zero deg ----------------
__global__ void detect_zero_kernel(const void* __restrict__ ei) {
    int i = blockIdx.x * blockDim.x + threadIdx.x;
    if (i < Nn) g_deg[i] = 0;
    if (blockIdx.x == 0 && threadIdx.x == 0) {
        const long long* p64 = (const long long*)ei;
        int ok64 = 1;
        for (int k = 0; k < 64; k++) {
            long long v = p64[k];
            if (v < 0 || v >= Nn) { ok64 = 0; break; }
        }
        g_is64 = ok64;
    }
}

// ---------------- x -> fp16 conversion (once) ----------------
__global__ void x_to_h16_kernel(const float* __restrict__ x) {
    int idx = blockIdx.x * blockDim.x + threadIdx.x;     // one float4 per thread
    if (idx < Nn * Hh / 4) {
        float4 v = ((const float4*)x)[idx];
        g_h16[idx * 2]     = __floats2half2_rn(v.x, v.y);
        g_h16[idx * 2 + 1] = __floats2half2_rn(v.z, v.w);
    }
}

// ---------------- CSR build ----------------
__global__ void count_deg_kernel(const void* __restrict__ ei) {
    int e = blockIdx.x * blockDim.x + threadIdx.x;
    if (e < Ee) {
        int dst = edge_at(ei, g_is64, (long long)Ee + e);
        atomicAdd(&g_deg[dst], 1);
    }
}

__global__ void scan_blocks_kernel() {
    __shared__ int s[1024];
    int t = threadIdx.x;
    int i = blockIdx.x * 1024 + t;
    int v = (i < Nn) ? g_deg[i] : 0;
    s[t] = v;
    __syncthreads();
    for (int off = 1; off < 1024; off <<= 1) {
        int add = (t >= off) ? s[t - off] : 0;
        __syncthreads();
        s[t] += add;
        __syncthreads();
    }
    if (i < Nn) g_row_ptr[i + 1] = s[t];
    if (t == 1023) g_bsums[blockIdx.x] = s[1023];
}

__global__ void scan_sums_kernel(int nb) {
    if (threadIdx.x == 0 && blockIdx.x == 0) {
        int acc = 0;
        for (int i = 0; i < nb; i++) { int tt = g_bsums[i]; g_bsums[i] = acc; acc += tt; }
    }
}

__global__ void scan_finalize_kernel() {
    int i = blockIdx.x * 1024 + threadIdx.x;
    if (i < Nn) {
        int incl = g_row_ptr[i + 1] + g_bsums[blockIdx.x];
        g_row_ptr[i + 1] = incl;
        int d = g_deg[i];
        g_cursor[i] = incl - d;
        g_inv_deg[i] = 1.0f / (float)(d > 1 ? d : 1);
        if (i == 0) g_row_ptr[0] = 0;
    }
}

__global__ void fill_csr_kernel(const void* __restrict__ ei) {
    int e = blockIdx.x * blockDim.x + threadIdx.x;
    if (e < Ee) {
        int is64 = g_is64;
        int dst = edge_at(ei, is64, (long long)Ee + e);
        int src = edge_at(ei, is64, e);
        int pos = atomicAdd(&g_cursor[dst], 1);
        g_col[pos] = src;
    }
}

// ---------------- mean aggregation: one warp per node, fp16 gather ----------------
__global__ __launch_bounds__(256) void aggregate_kernel() {
    int warp = (blockIdx.x * blockDim.x + threadIdx.x) >> 5;
    if (warp >= Nn) return;
    int lane = threadIdx.x & 31;
    int s = g_row_ptr[warp];
    int e = g_row_ptr[warp + 1];
    float4 acc = make_float4(0.f, 0.f, 0.f, 0.f);
    for (int i = s; i < e; i++) {
        int nbr = g_col[i];
        // 4 halves (8B) per lane -> 256B per warp, coalesced
        uint2 raw = *(const uint2*)(&g_h16[(size_t)nbr * 64 + lane * 2]);
        float2 f0 = __half22float2(*(const __half2*)&raw.x);
        float2 f1 = __half22float2(*(const __half2*)&raw.y);
        acc.x += f0.x; acc.y += f0.y; acc.z += f1.x; acc.w += f1.y;
    }
    float id = g_inv_deg[warp];
    acc.x *= id; acc.y *= id; acc.z *= id; acc.w *= id;
    // store fp32 pieces: lane covers cols [lane*4, lane*4+4)
    *(float4*)(g_agg + (size_t)warp * Hh + lane * 4) = acc;
}

// ---------------- tf32 tensor-core dual GEMM (raw fp32 bits -> tf32) ----------
// C = relu(A1@W1 [+ A2@W2] + b); BM=128,BN=128,BK=16; 8 warps, warp tile 32x64.
// writeH16 != 0 -> also emit fp16 copy of C into g_h16 (next layer's agg operand).
__global__ __launch_bounds__(256) void gemm_tf32_kernel(
    int selA1, const float* __restrict__ W1,
    int selA2, const float* __restrict__ W2,
    const float* __restrict__ bias, int selC,
    const float* __restrict__ x, int M, int writeH16)
{
    const float* A1 = rd_buf(selA1, x);
    const float* A2 = (selA2 < 0) ? A1 : rd_buf(selA2, x);
    float* C = wr_buf(selC);

    __shared__ float As[2][128][20];   // [stage][row][k], stride 20 -> conflict-free frags
    __shared__ float Bs[2][16][128];   // [stage][k][n], col XOR-swizzled by (k&3)<<3

    const int t = threadIdx.x;
    const int lane = t & 31;
    const int warp = t >> 5;
    const int g = lane >> 2;
    const int tig = lane & 3;
    const int warpM = warp & 3;
    const int warpN = warp >> 2;
    const int block_row = blockIdx.x * 128;

    const int nIter = (selA2 >= 0) ? 16 : 8;

    float acc[2][8][4];
#pragma unroll
    for (int mt = 0; mt < 2; mt++)
#pragma unroll
        for (int nt = 0; nt < 8; nt++)
#pragma unroll
            for (int i = 0; i < 4; i++) acc[mt][nt][i] = 0.f;

    uint32_t asA = (uint32_t)__cvta_generic_to_shared(&As[0][0][0]);
    uint32_t asB = (uint32_t)__cvta_generic_to_shared(&Bs[0][0][0]);

    auto issue = [&](int it, int s) {
        const float* Ap = (it < 8) ? A1 : A2;
        const float* Wp = (it < 8) ? W1 : W2;
        const int kk = (it & 7) * 16;
#pragma unroll
        for (int i = 0; i < 2; i++) {
            int idx = t + i * 256;
            int r = idx >> 2;
            int c4 = (idx & 3) * 4;
            int gr = block_row + r;
            int grc = (gr < M) ? gr : (M - 1);
            const float* src = Ap + (size_t)grc * 128 + kk + c4;
            uint32_t dst = asA + (uint32_t)(((s * 128 + r) * 20 + c4) * 4);
            int sz = (gr < M) ? 16 : 0;
            asm volatile("cp.async.cg.shared.global [%0], [%1], 16, %2;"
                         :: "r"(dst), "l"(src), "r"(sz));
        }
#pragma unroll
        for (int i = 0; i < 2; i++) {
            int idx = t + i * 256;
            int kr = idx >> 5;
            int n = (idx & 31) * 4;
            const float* src = Wp + (size_t)(kk + kr) * 128 + n;
            int pc = n ^ ((kr & 3) << 3);
            uint32_t dst = asB + (uint32_t)(((s * 16 + kr) * 128 + pc) * 4);
            asm volatile("cp.async.cg.shared.global [%0], [%1], 16;"
                         :: "r"(dst), "l"(src));
        }
        asm volatile("cp.async.commit_group;");
    };

    issue(0, 0);

    for (int it = 0; it < nIter; it++) {
        const int s = it & 1;
        if (it + 1 < nIter) {
            issue(it + 1, (it + 1) & 1);
            asm volatile("cp.async.wait_group 1;");
        } else {
            asm volatile("cp.async.wait_group 0;");
        }
        __syncthreads();

#pragma unroll
        for (int ks = 0; ks < 2; ks++) {
            const int kc = ks * 8 + tig;
            uint32_t af[2][4];
#pragma unroll
            for (int mt = 0; mt < 2; mt++) {
                int rb = warpM * 32 + mt * 16;
                af[mt][0] = __float_as_uint(As[s][rb + g][kc]);
                af[mt][1] = __float_as_uint(As[s][rb + g + 8][kc]);
                af[mt][2] = __float_as_uint(As[s][rb + g][kc + 4]);
                af[mt][3] = __float_as_uint(As[s][rb + g + 8][kc + 4]);
            }
            uint32_t bf[8][2];
            const int sw = (tig & 3) << 3;
#pragma unroll
            for (int nt = 0; nt < 8; nt++) {
                int nb = warpN * 64 + nt * 8 + g;
                bf[nt][0] = __float_as_uint(Bs[s][kc][nb ^ sw]);
                bf[nt][1] = __float_as_uint(Bs[s][kc + 4][nb ^ sw]);
            }
#pragma unroll
            for (int mt = 0; mt < 2; mt++)
#pragma unroll
                for (int nt = 0; nt < 8; nt++) {
                    asm volatile(
                        "mma.sync.aligned.m16n8k8.row.col.f32.tf32.tf32.f32 "
                        "{%0,%1,%2,%3}, {%4,%5,%6,%7}, {%8,%9}, {%0,%1,%2,%3};"
                        : "+f"(acc[mt][nt][0]), "+f"(acc[mt][nt][1]),
                          "+f"(acc[mt][nt][2]), "+f"(acc[mt][nt][3])
                        : "r"(af[mt][0]), "r"(af[mt][1]), "r"(af[mt][2]), "r"(af[mt][3]),
                          "r"(bf[nt][0]), "r"(bf[nt][1]));
                }
        }
        __syncthreads();
    }

    // -------- epilogue: bias + relu; fp32 store + optional fp16 copy --------
#pragma unroll
    for (int mt = 0; mt < 2; mt++) {
        int r0 = block_row + warpM * 32 + mt * 16 + g;
        int r1 = r0 + 8;
#pragma unroll
        for (int nt = 0; nt < 8; nt++) {
            int c0 = warpN * 64 + nt * 8 + 2 * tig;
            float2 bv = *(const float2*)(bias + c0);
            if (r0 < M) {
                float2 o;
                o.x = fmaxf(acc[mt][nt][0] + bv.x, 0.f);
                o.y = fmaxf(acc[mt][nt][1] + bv.y, 0.f);
                *(float2*)(C + (size_t)r0 * 128 + c0) = o;
                if (writeH16)
                    g_h16[((size_t)r0 * 128 + c0) / 2] = __floats2half2_rn(o.x, o.y);
            }
            if (r1 < M) {
                float2 o;
                o.x = fmaxf(acc[mt][nt][2] + bv.x, 0.f);
                o.y = fmaxf(acc[mt][nt][3] + bv.y, 0.f);
                *(float2*)(C + (size_t)r1 * 128 + c0) = o;
                if (writeH16)
                    g_h16[((size_t)r1 * 128 + c0) / 2] = __floats2half2_rn(o.x, o.y);
            }
        }
    }
}

// ---------------- fused lin2 + log_softmax: 32 rows per block ----------------
__global__ __launch_bounds__(320) void lin2_logsoftmax_kernel(
    const float* __restrict__ W, const float* __restrict__ b,
    float* __restrict__ outp, int M)
{
    __shared__ float Ws[128 * 40];
    __shared__ float bs[40];
    __shared__ float hs[32][128];
    __shared__ float logits[32][40];
    __shared__ float rmax[32], rlse[32];

    const int t = threadIdx.x;
    for (int i = t; i < 128 * 40; i += 320) Ws[i] = W[i];
    if (t < 40) bs[t] = b[t];

    const int row0 = blockIdx.x * 32;
    for (int i = t; i < 32 * 128; i += 320) {
        int r = i >> 7, c = i & 127;
        int gr = row0 + r;
        hs[r][c] = (gr < M) ? g_h2[(size_t)gr * 128 + c] : 0.f;
    }
    __syncthreads();

    const int j = t % 40;
    const int r0 = t / 40;
    float acc[4];
#pragma unroll
    for (int rr = 0; rr < 4; rr++) acc[rr] = bs[j];
#pragma unroll
    for (int k = 0; k < 128; k++) {
        float w = Ws[k * 40 + j];
#pragma unroll
        for (int rr = 0; rr < 4; rr++)
            acc[rr] += hs[r0 + rr * 8][k] * w;
    }
#pragma unroll
    for (int rr = 0; rr < 4; rr++)
        logits[r0 + rr * 8][j] = acc[rr];
    __syncthreads();

    if (t < 32) {
        float m = -1e30f;
#pragma unroll
        for (int jj = 0; jj < 40; jj++) m = fmaxf(m, logits[t][jj]);
        float s = 0.f;
#pragma unroll
        for (int jj = 0; jj < 40; jj++) s += expf(logits[t][jj] - m);
        rmax[t] = m;
        rlse[t] = logf(s);
    }
    __syncthreads();

#pragma unroll
    for (int rr = 0; rr < 4; rr++) {
        int r = r0 + rr * 8;
        int gr = row0 + r;
        if (gr < M)
            outp[(size_t)gr * 40 + j] = logits[r][j] - rmax[r] - rlse[r];
    }
}

// ---------------- launcher ----------------
extern "C" void kernel_launch(void* const* d_in, const int* in_sizes, int n_in,
                              void* d_out, int out_size) {
    const float* x  = (const float*)d_in[0];
    const void*  ei = d_in[1];
    const float *Wl1 = (const float*)d_in[2],  *bl1 = (const float*)d_in[3],  *Wr1 = (const float*)d_in[4];
    const float *Wl2 = (const float*)d_in[5],  *bl2 = (const float*)d_in[6],  *Wr2 = (const float*)d_in[7];
    const float *Wl3 = (const float*)d_in[8],  *bl3 = (const float*)d_in[9],  *Wr3 = (const float*)d_in[10];
    const float *Wlin1 = (const float*)d_in[11], *blin1 = (const float*)d_in[12];
    const float *Wlin2 = (const float*)d_in[13], *blin2 = (const float*)d_in[14];
    float* outp = (float*)d_out;

    const int TB = 256;
    const int edge_blocks = (Ee + TB - 1) / TB;
    const int node_blocks_1024 = (Nn + 1023) / 1024;
    const int node_blocks_256 = (Nn + 255) / 256;
    const int cvt_blocks = (Nn * Hh / 4 + TB - 1) / TB;
    const int agg_blocks = (Nn * 32 + TB - 1) / TB;   // one warp per node
    const int gemm_blocks = (Nn + 127) / 128;
    const int sm_blocks = (Nn + 31) / 32;

    // ---- CSR build + fp16 staging of x ----
    detect_zero_kernel<<<node_blocks_256, TB>>>(ei);
    x_to_h16_kernel<<<cvt_blocks, TB>>>(x);
    count_deg_kernel<<<edge_blocks, TB>>>(ei);
    scan_blocks_kernel<<<node_blocks_1024, 1024>>>();
    scan_sums_kernel<<<1, 32>>>(node_blocks_1024);
    scan_finalize_kernel<<<node_blocks_1024, 1024>>>();
    fill_csr_kernel<<<edge_blocks, TB>>>(ei);

    // selectors: 0 = g_agg, 1 = g_h1, 2 = g_h2, 3 = x
    // ---- layer 1: agg(x16) -> g_agg; h1 = relu(agg@Wl1 + x@Wr1 + b); also h16 ----
    aggregate_kernel<<<agg_blocks, TB>>>();
    gemm_tf32_kernel<<<gemm_blocks, 256>>>(0, Wl1, 3, Wr1, bl1, 1, x, Nn, 1);
    // ---- layer 2 ----
    aggregate_kernel<<<agg_blocks, TB>>>();
    gemm_tf32_kernel<<<gemm_blocks, 256>>>(0, Wl2, 1, Wr2, bl2, 2, x, Nn, 1);
    // ---- layer 3 (output h16 not needed further) ----
    aggregate_kernel<<<agg_blocks, TB>>>();
    gemm_tf32_kernel<<<gemm_blocks, 256>>>(0, Wl3, 2, Wr3, bl3, 1, x, Nn, 0);
    // ---- lin1 + relu ----
    gemm_tf32_kernel<<<gemm_blocks, 256>>>(1, Wlin1, -1, nullptr, blin1, 2, x, Nn, 0);
    // ---- lin2 + log_softmax ----
    lin2_logsoftmax_kernel<<<sm_blocks, 320>>>(Wlin2, blin2, outp, Nn);
}

// round 17
// speedup vs baseline: 1.3854x; 1.2080x over previous
#include <cuda_runtime.h>
#include <cuda_fp16.h>
#include <math.h>
#include <stdint.h>

#define Nn 50000
#define Ee 600000
#define Hh 128
#define Cc 40

// ---------------- scratch (static device globals; no allocation) ----------------
__device__ int    g_deg[Nn];
__device__ int    g_row_ptr[Nn + 1];
__device__ int    g_cursor[Nn];
__device__ int    g_col[Ee];
__device__ float  g_inv_deg[Nn];
__device__ int    g_bsums[64];
__device__ int    g_is64;
__device__ __half g_x16[(size_t)Nn * Hh];     // fp16 copy of x
__device__ __half g_a16[(size_t)Nn * Hh];     // aggregation output
__device__ __half g_fa[(size_t)Nn * Hh];      // hidden A
__device__ __half g_fb[(size_t)Nn * Hh];      // hidden B
__device__ __half g_W16[7][128 * 128];        // fp16 transposed weights [n*128+k]

// fp16 buffer selectors: 0 = g_a16, 1 = g_fa, 2 = g_fb, 3 = g_x16
__device__ __forceinline__ const __half* rd16(int sel) {
    switch (sel) {
        case 0: return g_a16;
        case 1: return g_fa;
        case 2: return g_fb;
        default: return g_x16;
    }
}
__device__ __forceinline__ __half* wr16(int sel) {
    switch (sel) {
        case 1: return g_fa;
        default: return g_fb;
    }
}

__device__ __forceinline__ int edge_at(const void* ei, int is64, long long idx) {
    if (is64) return (int)((const long long*)ei)[idx];
    return ((const int*)ei)[idx];
}

// ---------------- dtype detect + zero deg ----------------
__global__ void detect_zero_kernel(const void* __restrict__ ei) {
    int i = blockIdx.x * blockDim.x + threadIdx.x;
    if (i < Nn) g_deg[i] = 0;
    if (blockIdx.x == 0 && threadIdx.x == 0) {
        const long long* p64 = (const long long*)ei;
        int ok64 = 1;
        for (int k = 0; k < 64; k++) {
            long long v = p64[k];
            if (v < 0 || v >= Nn) { ok64 = 0; break; }
        }
        g_is64 = ok64;
    }
}

// ---------------- x -> fp16 (once per launch) ----------------
__global__ void x_to_h16_kernel(const float* __restrict__ x) {
    int idx = blockIdx.x * blockDim.x + threadIdx.x;     // one float4 per thread
    if (idx < Nn * Hh / 4) {
        float4 v = ((const float4*)x)[idx];
        __half2* dst = (__half2*)g_x16;
        dst[idx * 2]     = __floats2half2_rn(v.x, v.y);
        dst[idx * 2 + 1] = __floats2half2_rn(v.z, v.w);
    }
}

// ---------------- weight transpose + fp16 convert: g_W16[z][n*128+k] ----------------
__global__ void w_to_h16_kernel(const float* __restrict__ W0, const float* __restrict__ W1,
                                const float* __restrict__ W2, const float* __restrict__ W3,
                                const float* __restrict__ W4, const float* __restrict__ W5,
                                const float* __restrict__ W6) {
    const float* W;
    switch (blockIdx.z) {
        case 0: W = W0; break; case 1: W = W1; break; case 2: W = W2; break;
        case 3: W = W3; break; case 4: W = W4; break; case 5: W = W5; break;
        default: W = W6; break;
    }
    __shared__ float tile[32][33];
    int bn = blockIdx.x * 32;   // n block
    int bk = blockIdx.y * 32;   // k block
    int n = bn + threadIdx.x;
#pragma unroll
    for (int j = 0; j < 32; j += 8)
        tile[threadIdx.y + j][threadIdx.x] = W[(size_t)(bk + threadIdx.y + j) * 128 + n];
    __syncthreads();
    int k = bk + threadIdx.x;
    __half* o = g_W16[blockIdx.z];
#pragma unroll
    for (int j = 0; j < 32; j += 8)
        o[(size_t)(bn + threadIdx.y + j) * 128 + k] = __float2half(tile[threadIdx.x][threadIdx.y + j]);
}

// ---------------- CSR build ----------------
__global__ void count_deg_kernel(const void* __restrict__ ei) {
    int e = blockIdx.x * blockDim.x + threadIdx.x;
    if (e < Ee) {
        int dst = edge_at(ei, g_is64, (long long)Ee + e);
        atomicAdd(&g_deg[dst], 1);
    }
}

__global__ void scan_blocks_kernel() {
    __shared__ int s[1024];
    int t = threadIdx.x;
    int i = blockIdx.x * 1024 + t;
    int v = (i < Nn) ? g_deg[i] : 0;
    s[t] = v;
    __syncthreads();
    for (int off = 1; off < 1024; off <<= 1) {
        int add = (t >= off) ? s[t - off] : 0;
        __syncthreads();
        s[t] += add;
        __syncthreads();
    }
    if (i < Nn) g_row_ptr[i + 1] = s[t];
    if (t == 1023) g_bsums[blockIdx.x] = s[1023];
}

__global__ void scan_sums_kernel(int nb) {
    if (threadIdx.x == 0 && blockIdx.x == 0) {
        int acc = 0;
        for (int i = 0; i < nb; i++) { int tt = g_bsums[i]; g_bsums[i] = acc; acc += tt; }
    }
}

__global__ void scan_finalize_kernel() {
    int i = blockIdx.x * 1024 + threadIdx.x;
    if (i < Nn) {
        int incl = g_row_ptr[i + 1] + g_bsums[blockIdx.x];
        g_row_ptr[i + 1] = incl;
        int d = g_deg[i];
        g_cursor[i] = incl - d;
        g_inv_deg[i] = 1.0f / (float)(d > 1 ? d : 1);
        if (i == 0) g_row_ptr[0] = 0;
    }
}

__global__ void fill_csr_kernel(const void* __restrict__ ei) {
    int e = blockIdx.x * blockDim.x + threadIdx.x;
    if (e < Ee) {
        int is64 = g_is64;
        int dst = edge_at(ei, is64, (long long)Ee + e);
        int src = edge_at(ei, is64, e);
        int pos = atomicAdd(&g_cursor[dst], 1);
        g_col[pos] = src;
    }
}

// ---------------- mean aggregation: one warp per node, fp16 in/out, fp32 accum ----
__global__ __launch_bounds__(256) void aggregate_kernel(int selIn) {
    const __half* in = rd16(selIn);
    int warp = (blockIdx.x * blockDim.x + threadIdx.x) >> 5;
    if (warp >= Nn) return;
    int lane = threadIdx.x & 31;
    int s = g_row_ptr[warp];
    int e = g_row_ptr[warp + 1];
    float4 acc = make_float4(0.f, 0.f, 0.f, 0.f);
    for (int i = s; i < e; i++) {
        int nbr = g_col[i];
        uint2 raw = *(const uint2*)(in + (size_t)nbr * Hh + lane * 4);  // 8B/lane
        float2 f0 = __half22float2(*(const __half2*)&raw.x);
        float2 f1 = __half22float2(*(const __half2*)&raw.y);
        acc.x += f0.x; acc.y += f0.y; acc.z += f1.x; acc.w += f1.y;
    }
    float id = g_inv_deg[warp];
    __half2 h0 = __floats2half2_rn(acc.x * id, acc.y * id);
    __half2 h1 = __floats2half2_rn(acc.z * id, acc.w * id);
    uint2 packed = make_uint2(*(uint32_t*)&h0, *(uint32_t*)&h1);
    *(uint2*)(g_a16 + (size_t)warp * Hh + lane * 4) = packed;
}

// ---------------- fp16 tensor-core dual GEMM --------------------------------
// C = relu(A1@W1 [+ A2@W2] + b); BM=128, BN=128, BK=32 halves; 8 warps, warp 32x64.
// A fp16 row-major [M,128]; W fp16 transposed [n][k]; accum fp32; out fp16.
#define APITCH 40   // halves per smem row (80B -> conflict-free fragment LDS)

__global__ __launch_bounds__(256) void gemm_f16_kernel(
    int selA1, int w1, int selA2, int w2,
    const float* __restrict__ bias, int selC, int M)
{
    const __half* A1 = rd16(selA1);
    const __half* A2 = (selA2 < 0) ? A1 : rd16(selA2);
    const __half* B1 = g_W16[w1];
    const __half* B2 = (w2 < 0) ? B1 : g_W16[w2];
    __half* C = wr16(selC);

    __shared__ __align__(16) __half As[2][128][APITCH];
    __shared__ __align__(16) __half Bs[2][128][APITCH];

    const int t = threadIdx.x;
    const int lane = t & 31;
    const int warp = t >> 5;
    const int g = lane >> 2;       // groupID 0..7
    const int tig = lane & 3;      // threadID_in_group 0..3
    const int warpM = warp & 3;    // 4 warps over M
    const int warpN = warp >> 2;   // 2 warps over N
    const int block_row = blockIdx.x * 128;

    const int nIter = (selA2 >= 0) ? 8 : 4;   // BK=32 stages

    float acc[2][8][4];
#pragma unroll
    for (int mt = 0; mt < 2; mt++)
#pragma unroll
        for (int nt = 0; nt < 8; nt++)
#pragma unroll
            for (int i = 0; i < 4; i++) acc[mt][nt][i] = 0.f;

    uint32_t asA = (uint32_t)__cvta_generic_to_shared(&As[0][0][0]);
    uint32_t asB = (uint32_t)__cvta_generic_to_shared(&Bs[0][0][0]);
    const uint32_t stageBytes = 128 * APITCH * 2;

    // per stage: A 128 rows x 64B (4 x 16B chunks), B same -> 2+2 chunks/thread
    auto issue = [&](int it, int s) {
        const __half* Ap = (it < 4) ? A1 : A2;
        const __half* Wp = (it < 4) ? B1 : B2;
        const int kk = (it & 3) * 32;
#pragma unroll
        for (int i = 0; i < 2; i++) {
            int idx = t + i * 256;
            int r = idx >> 2;              // 0..127
            int c = idx & 3;               // 16B chunk = 8 halves
            int gr = block_row + r;
            int grc = (gr < M) ? gr : (M - 1);
            const __half* src = Ap + (size_t)grc * 128 + kk + c * 8;
            uint32_t dst = asA + s * stageBytes + (uint32_t)((r * APITCH + c * 8) * 2);
            int sz = (gr < M) ? 16 : 0;
            asm volatile("cp.async.cg.shared.global [%0], [%1], 16, %2;"
                         :: "r"(dst), "l"(src), "r"(sz));
        }
#pragma unroll
        for (int i = 0; i < 2; i++) {
            int idx = t + i * 256;
            int r = idx >> 2;
            int c = idx & 3;
            const __half* src = Wp + (size_t)r * 128 + kk + c * 8;
            uint32_t dst = asB + s * stageBytes + (uint32_t)((r * APITCH + c * 8) * 2);
            asm volatile("cp.async.cg.shared.global [%0], [%1], 16;"
                         :: "r"(dst), "l"(src));
        }
        asm volatile("cp.async.commit_group;");
    };

    issue(0, 0);

    for (int it = 0; it < nIter; it++) {
        const int s = it & 1;
        if (it + 1 < nIter) {
            issue(it + 1, (it + 1) & 1);
            asm volatile("cp.async.wait_group 1;");
        } else {
            asm volatile("cp.async.wait_group 0;");
        }
        __syncthreads();

#pragma unroll
        for (int ks = 0; ks < 2; ks++) {           // two K=16 steps per BK=32
            const int kc = ks * 16 + tig * 2;
            uint32_t af[2][4];
#pragma unroll
            for (int mt = 0; mt < 2; mt++) {
                int rb = warpM * 32 + mt * 16;
                af[mt][0] = *(const uint32_t*)&As[s][rb + g][kc];
                af[mt][1] = *(const uint32_t*)&As[s][rb + g + 8][kc];
                af[mt][2] = *(const uint32_t*)&As[s][rb + g][kc + 8];
                af[mt][3] = *(const uint32_t*)&As[s][rb + g + 8][kc + 8];
            }
            uint32_t bf[8][2];
#pragma unroll
            for (int nt = 0; nt < 8; nt++) {
                int nb = warpN * 64 + nt * 8 + g;
                bf[nt][0] = *(const uint32_t*)&Bs[s][nb][kc];
                bf[nt][1] = *(const uint32_t*)&Bs[s][nb][kc + 8];
            }
#pragma unroll
            for (int mt = 0; mt < 2; mt++)
#pragma unroll
                for (int nt = 0; nt < 8; nt++) {
                    asm volatile(
                        "mma.sync.aligned.m16n8k16.row.col.f32.f16.f16.f32 "
                        "{%0,%1,%2,%3}, {%4,%5,%6,%7}, {%8,%9}, {%0,%1,%2,%3};"
                        : "+f"(acc[mt][nt][0]), "+f"(acc[mt][nt][1]),
                          "+f"(acc[mt][nt][2]), "+f"(acc[mt][nt][3])
                        : "r"(af[mt][0]), "r"(af[mt][1]), "r"(af[mt][2]), "r"(af[mt][3]),
                          "r"(bf[nt][0]), "r"(bf[nt][1]));
                }
        }
        __syncthreads();
    }

    // -------- epilogue: bias + relu, fp16 half2 stores --------
#pragma unroll
    for (int mt = 0; mt < 2; mt++) {
        int r0 = block_row + warpM * 32 + mt * 16 + g;
        int r1 = r0 + 8;
#pragma unroll
        for (int nt = 0; nt < 8; nt++) {
            int c0 = warpN * 64 + nt * 8 + 2 * tig;
            float2 bv = *(const float2*)(bias + c0);
            if (r0 < M) {
                __half2 o = __floats2half2_rn(fmaxf(acc[mt][nt][0] + bv.x, 0.f),
                                              fmaxf(acc[mt][nt][1] + bv.y, 0.f));
                *(__half2*)(C + (size_t)r0 * 128 + c0) = o;
            }
            if (r1 < M) {
                __half2 o = __floats2half2_rn(fmaxf(acc[mt][nt][2] + bv.x, 0.f),
                                              fmaxf(acc[mt][nt][3] + bv.y, 0.f));
                *(__half2*)(C + (size_t)r1 * 128 + c0) = o;
            }
        }
    }
}

// ---------------- fused lin2 + log_softmax: 32 rows per block (reads g_fb fp16) ----
__global__ __launch_bounds__(320) void lin2_logsoftmax_kernel(
    const float* __restrict__ W, const float* __restrict__ b,
    float* __restrict__ outp, int M)
{
    __shared__ float Ws[128 * 40];
    __shared__ float bs[40];
    __shared__ float hs[32][128];
    __shared__ float logits[32][40];
    __shared__ float rmax[32], rlse[32];

    const int t = threadIdx.x;
    for (int i = t; i < 128 * 40; i += 320) Ws[i] = W[i];
    if (t < 40) bs[t] = b[t];

    const int row0 = blockIdx.x * 32;
    for (int i = t; i < 32 * 128; i += 320) {
        int r = i >> 7, c = i & 127;
        int gr = row0 + r;
        hs[r][c] = (gr < M) ? __half2float(g_fb[(size_t)gr * 128 + c]) : 0.f;
    }
    __syncthreads();

    const int j = t % 40;
    const int r0 = t / 40;
    float acc[4];
#pragma unroll
    for (int rr = 0; rr < 4; rr++) acc[rr] = bs[j];
#pragma unroll
    for (int k = 0; k < 128; k++) {
        float w = Ws[k * 40 + j];
#pragma unroll
        for (int rr = 0; rr < 4; rr++)
            acc[rr] += hs[r0 + rr * 8][k] * w;
    }
#pragma unroll
    for (int rr = 0; rr < 4; rr++)
        logits[r0 + rr * 8][j] = acc[rr];
    __syncthreads();

    if (t < 32) {
        float m = -1e30f;
#pragma unroll
        for (int jj = 0; jj < 40; jj++) m = fmaxf(m, logits[t][jj]);
        float s = 0.f;
#pragma unroll
        for (int jj = 0; jj < 40; jj++) s += expf(logits[t][jj] - m);
        rmax[t] = m;
        rlse[t] = logf(s);
    }
    __syncthreads();

#pragma unroll
    for (int rr = 0; rr < 4; rr++) {
        int r = r0 + rr * 8;
        int gr = row0 + r;
        if (gr < M)
            outp[(size_t)gr * 40 + j] = logits[r][j] - rmax[r] - rlse[r];
    }
}

// ---------------- launcher ----------------
extern "C" void kernel_launch(void* const* d_in, const int* in_sizes, int n_in,
                              void* d_out, int out_size) {
    const float* x  = (const float*)d_in[0];
    const void*  ei = d_in[1];
    const float *Wl1 = (const float*)d_in[2],  *bl1 = (const float*)d_in[3],  *Wr1 = (const float*)d_in[4];
    const float *Wl2 = (const float*)d_in[5],  *bl2 = (const float*)d_in[6],  *Wr2 = (const float*)d_in[7];
    const float *Wl3 = (const float*)d_in[8],  *bl3 = (const float*)d_in[9],  *Wr3 = (const float*)d_in[10];
    const float *Wlin1 = (const float*)d_in[11], *blin1 = (const float*)d_in[12];
    const float *Wlin2 = (const float*)d_in[13], *blin2 = (const float*)d_in[14];
    float* outp = (float*)d_out;

    const int TB = 256;
    const int edge_blocks = (Ee + TB - 1) / TB;
    const int node_blocks_1024 = (Nn + 1023) / 1024;
    const int node_blocks_256 = (Nn + 255) / 256;
    const int cvt_blocks = (Nn * Hh / 4 + TB - 1) / TB;
    const int agg_blocks = (Nn * 32 + TB - 1) / TB;   // one warp per node
    const int gemm_blocks = (Nn + 127) / 128;
    const int sm_blocks = (Nn + 31) / 32;

    // ---- staging + CSR build ----
    detect_zero_kernel<<<node_blocks_256, TB>>>(ei);
    x_to_h16_kernel<<<cvt_blocks, TB>>>(x);
    {
        dim3 tg(4, 4, 7), tb(32, 8);
        w_to_h16_kernel<<<tg, tb>>>(Wl1, Wr1, Wl2, Wr2, Wl3, Wr3, Wlin1);
    }
    count_deg_kernel<<<edge_blocks, TB>>>(ei);
    scan_blocks_kernel<<<node_blocks_1024, 1024>>>();
    scan_sums_kernel<<<1, 32>>>(node_blocks_1024);
    scan_finalize_kernel<<<node_blocks_1024, 1024>>>();
    fill_csr_kernel<<<edge_blocks, TB>>>(ei);

    // fp16 selectors: 0 = g_a16, 1 = g_fa, 2 = g_fb, 3 = g_x16 ; weights by g_W16 idx
    // ---- layer 1: agg(x16)->a16; fa = relu(a16@Wl1 + x16@Wr1 + b) ----
    aggregate_kernel<<<agg_blocks, TB>>>(3);
    gemm_f16_kernel<<<gemm_blocks, 256>>>(0, 0, 3, 1, bl1, 1, Nn);
    // ---- layer 2: agg(fa)->a16; fb = relu(a16@Wl2 + fa@Wr2 + b) ----
    aggregate_kernel<<<agg_blocks, TB>>>(1);
    gemm_f16_kernel<<<gemm_blocks, 256>>>(0, 2, 1, 3, bl2, 2, Nn);
    // ---- layer 3: agg(fb)->a16; fa = relu(a16@Wl3 + fb@Wr3 + b) ----
    aggregate_kernel<<<agg_blocks, TB>>>(2);
    gemm_f16_kernel<<<gemm_blocks, 256>>>(0, 4, 2, 5, bl3, 1, Nn);
    // ---- lin1 + relu: fb = relu(fa @ Wlin1 + b) ----
    gemm_f16_kernel<<<gemm_blocks, 256>>>(1, 6, -1, -1, blin1, 2, Nn);
    // ---- lin2 + log_softmax (reads g_fb) ----
    lin2_logsoftmax_kernel<<<sm_blocks, 320>>>(Wlin2, blin2, outp, Nn);
}